// round 1
// baseline (speedup 1.0000x reference)
#include <cuda_runtime.h>
#include <math_constants.h>
#include <cstdint>

#define NROWS 8192
#define DIM 128
#define BM 128
#define BN 128
#define SA 129            // A smem row stride (odd -> ty halves on distinct banks)
#define SB 130            // B smem row stride (==2 mod 4 -> conflict-free b reads)
#define NSPLIT 2
#define COLS_PER_SPLIT (NROWS / NSPLIT)
#define TILES (COLS_PER_SPLIT / BN)   // 32
#define MARGIN_F 0.3f

// Scratch (device globals; no allocation allowed)
__device__ float g_sq1[NROWS];
__device__ float g_sq2[NROWS];
__device__ float g_posv[NROWS];                 // sq2[i] - 2*dot(i,i)
__device__ float g_rowmin[NSPLIT][NROWS];       // min_j (sq2[j]-2*dot) per split

typedef unsigned long long u64;

__device__ __forceinline__ u64 pk2(float lo, float hi) {
    u64 r; asm("mov.b64 %0, {%1, %2};" : "=l"(r) : "f"(lo), "f"(hi)); return r;
}
__device__ __forceinline__ void fma2(u64& d, u64 a, u64 b) {
    asm("fma.rn.f32x2 %0, %1, %2, %0;" : "+l"(d) : "l"(a), "l"(b));
}
__device__ __forceinline__ void upk2(u64 v, float& lo, float& hi) {
    asm("mov.b64 {%0, %1}, %2;" : "=f"(lo), "=f"(hi) : "l"(v));
}

// ---------------------------------------------------------------------------
// Kernel 1: per-row squared norms of z1 and z2 (one warp per row)
// ---------------------------------------------------------------------------
__global__ void sq_kernel(const float* __restrict__ z1, const float* __restrict__ z2) {
    int gw = (blockIdx.x * blockDim.x + threadIdx.x) >> 5;
    int lane = threadIdx.x & 31;
    if (gw >= NROWS) return;
    const float4* r1 = reinterpret_cast<const float4*>(z1 + (size_t)gw * DIM);
    const float4* r2 = reinterpret_cast<const float4*>(z2 + (size_t)gw * DIM);
    float4 v = r1[lane];
    float s = v.x * v.x + v.y * v.y + v.z * v.z + v.w * v.w;
    #pragma unroll
    for (int o = 16; o; o >>= 1) s += __shfl_xor_sync(0xffffffffu, s, o);
    if (lane == 0) g_sq1[gw] = s;
    v = r2[lane];
    s = v.x * v.x + v.y * v.y + v.z * v.z + v.w * v.w;
    #pragma unroll
    for (int o = 16; o; o >>= 1) s += __shfl_xor_sync(0xffffffffu, s, o);
    if (lane == 0) g_sq2[gw] = s;
}

// ---------------------------------------------------------------------------
// Kernel 2: tiled cross-GEMM with fused min/diag epilogue.
// Block = 128 rows x (NROWS/NSPLIT) cols. Grid (64, NSPLIT) = 128 blocks.
// f32x2 packed FMA (FFMA2) microkernel: 8x8 per thread = 8x4 u64 accumulators.
// ---------------------------------------------------------------------------
__global__ __launch_bounds__(256, 1)
void tl_main_kernel(const float* __restrict__ z1, const float* __restrict__ z2) {
    extern __shared__ float smem[];
    float* As = smem;                              // BM * SA
    float* Bs0 = smem + BM * SA;                   // BN * SB (double buffered)
    float* Bs1 = Bs0 + BN * SB;

    const int tid = threadIdx.x;
    const int tx = tid & 15;       // 16 column groups
    const int ty = tid >> 4;       // 16 row groups
    const int rowBase = blockIdx.x * BM;
    const int sp = blockIdx.y;
    const int colBase = sp * COLS_PER_SPLIT;

    // --- Load A tile: 128 rows x 128 cols == one contiguous 64KB block of z1
    {
        const float4* Ag = reinterpret_cast<const float4*>(z1 + (size_t)rowBase * DIM);
        #pragma unroll
        for (int e = 0; e < 16; e++) {
            int g4 = e * 256 + tid;            // 0..4095 float4s
            float4 v = Ag[g4];
            int n = g4 >> 5;                   // row in tile
            int k = (g4 & 31) * 4;             // col
            float* dst = As + n * SA + k;
            dst[0] = v.x; dst[1] = v.y; dst[2] = v.z; dst[3] = v.w;
        }
    }

    uint32_t bsm0 = (uint32_t)__cvta_generic_to_shared(Bs0);
    uint32_t bsm1 = (uint32_t)__cvta_generic_to_shared(Bs1);

    auto loadB = [&](int jt, int buf) {
        const float* Bg = z2 + (size_t)(colBase + jt * BN) * DIM;  // contiguous 64KB
        uint32_t base = buf ? bsm1 : bsm0;
        #pragma unroll
        for (int e = 0; e < 32; e++) {
            int g8 = e * 256 + tid;            // 0..8191 float2s
            int n = g8 >> 6;
            int k = (g8 & 63) * 2;
            uint32_t dst = base + (uint32_t)(n * SB + k) * 4u;
            const float* src = Bg + (size_t)g8 * 2;
            asm volatile("cp.async.ca.shared.global [%0], [%1], 8;\n"
                         :: "r"(dst), "l"(src));
        }
        asm volatile("cp.async.commit_group;\n" ::: "memory");
    };

    loadB(0, 0);

    float rmin[8];
    #pragma unroll
    for (int r = 0; r < 8; r++) rmin[r] = CUDART_INF_F;

    const float* aBase = As + (ty * 8) * SA;

    for (int jt = 0; jt < TILES; jt++) {
        asm volatile("cp.async.wait_group 0;\n" ::: "memory");
        __syncthreads();
        if (jt + 1 < TILES) loadB(jt + 1, (jt + 1) & 1);

        const float* bBase = ((jt & 1) ? Bs1 : Bs0) + tx * SB;

        u64 acc[8][4];
        #pragma unroll
        for (int r = 0; r < 8; r++)
            #pragma unroll
            for (int c = 0; c < 4; c++) acc[r][c] = 0ull;

        #pragma unroll 1
        for (int k0 = 0; k0 < DIM; k0 += 16) {
            #pragma unroll
            for (int kk = 0; kk < 16; kk++) {
                const int k = k0 + kk;
                float a[8], b[8];
                #pragma unroll
                for (int r = 0; r < 8; r++) a[r] = aBase[r * SA + k];
                #pragma unroll
                for (int c = 0; c < 8; c++) b[c] = bBase[c * 16 * SB + k];
                u64 bp[4];
                #pragma unroll
                for (int c = 0; c < 4; c++) bp[c] = pk2(b[2 * c], b[2 * c + 1]);
                #pragma unroll
                for (int r = 0; r < 8; r++) {
                    u64 av = pk2(a[r], a[r]);
                    #pragma unroll
                    for (int c = 0; c < 4; c++) fma2(acc[r][c], av, bp[c]);
                }
            }
        }

        // --- fused epilogue: val = sq2[j] - 2*dot ; mask diagonal; running min
        const int jcol = colBase + jt * BN + tx;
        float s2[8];
        #pragma unroll
        for (int c = 0; c < 8; c++) s2[c] = g_sq2[jcol + 16 * c];
        #pragma unroll
        for (int r = 0; r < 8; r++) {
            const int ig = rowBase + ty * 8 + r;
            #pragma unroll
            for (int cp = 0; cp < 4; cp++) {
                float d0, d1;
                upk2(acc[r][cp], d0, d1);
                float v0 = s2[2 * cp]     - 2.0f * d0;
                float v1 = s2[2 * cp + 1] - 2.0f * d1;
                const int j0 = jcol + 16 * (2 * cp);
                const int j1 = jcol + 16 * (2 * cp + 1);
                if (j0 == ig) { g_posv[ig] = v0; v0 = CUDART_INF_F; }
                if (j1 == ig) { g_posv[ig] = v1; v1 = CUDART_INF_F; }
                rmin[r] = fminf(rmin[r], fminf(v0, v1));
            }
        }
    }

    // reduce per-row min across the 16 tx lanes (within 16-lane groups)
    #pragma unroll
    for (int r = 0; r < 8; r++) {
        float v = rmin[r];
        #pragma unroll
        for (int o = 8; o; o >>= 1)
            v = fminf(v, __shfl_xor_sync(0xffffffffu, v, o, 16));
        if (tx == 0) g_rowmin[sp][rowBase + ty * 8 + r] = v;
    }
}

// ---------------------------------------------------------------------------
// Kernel 3: combine splits, compute hinge loss, deterministic mean
// ---------------------------------------------------------------------------
__global__ void finalize_kernel(float* __restrict__ out) {
    __shared__ float red[256];
    const int tid = threadIdx.x;
    float s = 0.f;
    for (int i = tid; i < NROWS; i += 256) {
        float m = g_rowmin[0][i];
        #pragma unroll
        for (int sp = 1; sp < NSPLIT; sp++) m = fminf(m, g_rowmin[sp][i]);
        const float sq1 = g_sq1[i];
        const float pos_d2 = sq1 + g_posv[i];
        const float neg_d2 = sq1 + m;
        const float l = sqrtf(fmaxf(pos_d2, 0.f)) - sqrtf(fmaxf(neg_d2, 0.f)) + MARGIN_F;
        s += fmaxf(l, 0.f);
    }
    red[tid] = s;
    __syncthreads();
    #pragma unroll
    for (int o = 128; o; o >>= 1) {
        if (tid < o) red[tid] += red[tid + o];
        __syncthreads();
    }
    if (tid == 0) out[0] = red[0] / (float)NROWS;
}

// ---------------------------------------------------------------------------
extern "C" void kernel_launch(void* const* d_in, const int* in_sizes, int n_in,
                              void* d_out, int out_size) {
    const float* z1 = (const float*)d_in[0];
    const float* z2 = (const float*)d_in[1];
    float* out = (float*)d_out;

    const size_t smem = (size_t)(BM * SA + 2 * BN * SB) * sizeof(float); // ~199 KB
    cudaFuncSetAttribute(tl_main_kernel,
                         cudaFuncAttributeMaxDynamicSharedMemorySize, (int)smem);

    sq_kernel<<<NROWS / 8, 256>>>(z1, z2);
    tl_main_kernel<<<dim3(NROWS / BM, NSPLIT), 256, smem>>>(z1, z2);
    finalize_kernel<<<1, 256>>>(out);
}

// round 3
// speedup vs baseline: 2.8468x; 2.8468x over previous
#include <cuda_runtime.h>
#include <cuda_bf16.h>
#include <math_constants.h>
#include <cstdint>

#define NROWS 8192
#define DIM 128
#define NSPLIT 2
#define TILES 32                  // 128-wide col tiles per split
#define MARGIN_F 0.3f

#define AB_ROW 272                // padded row: 136 bf16 (128 used) -> conflict-free ldmatrix
#define CHB (128 * AB_ROW)        // 34816 B per 128x128 bf16 chunk
#define NCHUNK 3                  // K = 384 = 3 x 128  (hi|lo|hi) x (hi|hi|lo)
#define ABLK (NCHUNK * CHB)       // 104448 B per 128-row block
#define TOTAL_CC (TILES * NCHUNK) // 96

// smem: partmin[4][128] floats (2048 B) | A block (ABLK) | B double buf (2*CHB)
#define SM_PART 0
#define SM_A 2048
#define SM_B (SM_A + ABLK)
#define SMEM_TOTAL (SM_B + 2 * CHB)   // 176128

typedef unsigned long long u64;

__device__ __align__(16) unsigned char g_A[64 * ABLK];   // ~6.4 MB
__device__ __align__(16) unsigned char g_B[64 * ABLK];
__device__ float g_sq1[NROWS];
__device__ float g_sq2[NROWS];
__device__ float g_posv[NROWS];
__device__ float g_rowmin[NSPLIT][NROWS];

__device__ __forceinline__ uint32_t smem_u32(const void* p) {
    uint32_t a;
    asm("{ .reg .u64 t; cvta.to.shared.u64 t, %1; cvt.u32.u64 %0, t; }" : "=r"(a) : "l"(p));
    return a;
}
__device__ __forceinline__ void cpasync16(uint32_t dst, const void* src) {
    asm volatile("cp.async.cg.shared.global [%0], [%1], 16;" :: "r"(dst), "l"(src));
}
#define CP_COMMIT() asm volatile("cp.async.commit_group;" ::: "memory")
#define CP_WAIT0()  asm volatile("cp.async.wait_group 0;"  ::: "memory")

__device__ __forceinline__ void ldsm_x4(uint32_t addr, uint32_t& r0, uint32_t& r1,
                                        uint32_t& r2, uint32_t& r3) {
    asm volatile("ldmatrix.sync.aligned.m8n8.x4.shared.b16 {%0,%1,%2,%3}, [%4];"
                 : "=r"(r0), "=r"(r1), "=r"(r2), "=r"(r3) : "r"(addr));
}
__device__ __forceinline__ void mma16816(float* c, uint32_t a0, uint32_t a1, uint32_t a2,
                                         uint32_t a3, uint32_t b0, uint32_t b1) {
    asm volatile("mma.sync.aligned.m16n8k16.row.col.f32.bf16.bf16.f32 "
                 "{%0,%1,%2,%3}, {%4,%5,%6,%7}, {%8,%9}, {%0,%1,%2,%3};"
                 : "+f"(c[0]), "+f"(c[1]), "+f"(c[2]), "+f"(c[3])
                 : "r"(a0), "r"(a1), "r"(a2), "r"(a3), "r"(b0), "r"(b1));
}

// ---------------------------------------------------------------------------
// Prep: one warp per row; sq norms + bf16 hi/lo split into padded row-major
// blocks: layout [rowblock][chunk 0..2][row 0..127][136 bf16].
// A chunks = (hi, lo, hi) ; B chunks = (hi, hi, lo).
// ---------------------------------------------------------------------------
__global__ void prep_kernel(const float* __restrict__ z1, const float* __restrict__ z2) {
    const int gw = (blockIdx.x * blockDim.x + threadIdx.x) >> 5;
    const int l  = threadIdx.x & 31;
    if (gw >= NROWS) return;
    const int rb = gw >> 7, r = gw & 127;
    const size_t base = (size_t)rb * ABLK + (size_t)r * AB_ROW + (size_t)l * 8;

    {   // z1 -> A
        float4 v = reinterpret_cast<const float4*>(z1 + (size_t)gw * DIM)[l];
        float s = v.x * v.x + v.y * v.y + v.z * v.z + v.w * v.w;
        #pragma unroll
        for (int o = 16; o; o >>= 1) s += __shfl_xor_sync(0xffffffffu, s, o);
        if (l == 0) g_sq1[gw] = s;
        float x[4] = {v.x, v.y, v.z, v.w};
        u64 hq = 0, lq = 0;
        #pragma unroll
        for (int t = 0; t < 4; t++) {
            __nv_bfloat16 h  = __float2bfloat16_rn(x[t]);
            __nv_bfloat16 lo = __float2bfloat16_rn(x[t] - __bfloat162float(h));
            hq |= (u64)__bfloat16_as_ushort(h)  << (16 * t);
            lq |= (u64)__bfloat16_as_ushort(lo) << (16 * t);
        }
        *(u64*)(g_A + base + 0 * CHB) = hq;
        *(u64*)(g_A + base + 1 * CHB) = lq;
        *(u64*)(g_A + base + 2 * CHB) = hq;
    }
    {   // z2 -> B
        float4 v = reinterpret_cast<const float4*>(z2 + (size_t)gw * DIM)[l];
        float s = v.x * v.x + v.y * v.y + v.z * v.z + v.w * v.w;
        #pragma unroll
        for (int o = 16; o; o >>= 1) s += __shfl_xor_sync(0xffffffffu, s, o);
        if (l == 0) g_sq2[gw] = s;
        float x[4] = {v.x, v.y, v.z, v.w};
        u64 hq = 0, lq = 0;
        #pragma unroll
        for (int t = 0; t < 4; t++) {
            __nv_bfloat16 h  = __float2bfloat16_rn(x[t]);
            __nv_bfloat16 lo = __float2bfloat16_rn(x[t] - __bfloat162float(h));
            hq |= (u64)__bfloat16_as_ushort(h)  << (16 * t);
            lq |= (u64)__bfloat16_as_ushort(lo) << (16 * t);
        }
        *(u64*)(g_B + base + 0 * CHB) = hq;
        *(u64*)(g_B + base + 1 * CHB) = hq;
        *(u64*)(g_B + base + 2 * CHB) = lq;
    }
}

// ---------------------------------------------------------------------------
// Main: 128 CTAs (64 row-blocks x 2 col-splits), 256 threads = 8 warps.
// Warp tile 64x32 via mma.sync m16n8k16 bf16. Fused row-min epilogue in regs.
// ---------------------------------------------------------------------------
__global__ __launch_bounds__(256, 1) void tl_gemm_kernel() {
    extern __shared__ char smem[];
    float* partmin = (float*)(smem + SM_PART);
    const uint32_t smA = smem_u32(smem) + SM_A;
    const uint32_t smB = smem_u32(smem) + SM_B;

    const int tid = threadIdx.x;
    const int l = tid & 31, wid = tid >> 5;
    const int wr = wid & 1, wc = wid >> 1;        // 2 row halves x 4 col groups
    const int rowBase = blockIdx.x * 128;
    const int sp = blockIdx.y;

    // prologue: A block (resident) + B tile0/chunk0, one commit group
    {
        const unsigned char* Ag = g_A + (size_t)blockIdx.x * ABLK;
        #pragma unroll
        for (int e = 0; e < 26; e++) {
            int idx = e * 256 + tid;                   // 6528 x 16B
            if (idx < ABLK / 16) cpasync16(smA + idx * 16, Ag + (size_t)idx * 16);
        }
        const unsigned char* Bg = g_B + (size_t)(sp * TILES) * ABLK;
        #pragma unroll
        for (int e = 0; e < 9; e++) {
            int idx = e * 256 + tid;                   // 2176 x 16B
            if (idx < CHB / 16) cpasync16(smB + idx * 16, Bg + (size_t)idx * 16);
        }
        CP_COMMIT();
    }

    float acc[4][4][4];
    #pragma unroll
    for (int i = 0; i < 4; i++)
        #pragma unroll
        for (int j = 0; j < 4; j++)
            #pragma unroll
            for (int c = 0; c < 4; c++) acc[i][j][c] = 0.f;
    float rminL[4], rminH[4];
    #pragma unroll
    for (int i = 0; i < 4; i++) { rminL[i] = CUDART_INF_F; rminH[i] = CUDART_INF_F; }

    // ldmatrix base addresses (lane-mapped)
    const uint32_t aBase = smA + (uint32_t)((wr * 64 + (l & 15)) * AB_ROW + (l >> 4) * 16);
    const uint32_t bBase = smB + (uint32_t)((wc * 32 + (l & 15)) * AB_ROW + (l >> 4) * 16);

    for (int cc = 0; cc < TOTAL_CC; cc++) {
        const int jt = cc / 3, kc = cc - jt * 3;

        CP_WAIT0();
        __syncthreads();              // chunk cc ready; all warps done with buf (cc+1)&1

        if (cc + 1 < TOTAL_CC) {      // prefetch next chunk, overlaps compute below
            const int cn = cc + 1, jt2 = cn / 3, kc2 = cn - jt2 * 3;
            const unsigned char* Bg = g_B + ((size_t)(sp * TILES + jt2) * NCHUNK + kc2) * CHB;
            const uint32_t dst = smB + (uint32_t)((cn & 1) ? CHB : 0);
            #pragma unroll
            for (int e = 0; e < 9; e++) {
                int idx = e * 256 + tid;
                if (idx < CHB / 16) cpasync16(dst + idx * 16, Bg + (size_t)idx * 16);
            }
            CP_COMMIT();
        }

        const uint32_t aC = aBase + (uint32_t)kc * CHB;
        const uint32_t bC = bBase + (uint32_t)((cc & 1) ? CHB : 0);

        #pragma unroll
        for (int ks = 0; ks < 8; ks++) {
            uint32_t b[8];
            ldsm_x4(bC + ks * 32, b[0], b[1], b[2], b[3]);                 // n0-15
            ldsm_x4(bC + 16 * AB_ROW + ks * 32, b[4], b[5], b[6], b[7]);   // n16-31
            #pragma unroll
            for (int i = 0; i < 4; i++) {
                uint32_t a0, a1, a2, a3;
                ldsm_x4(aC + i * 16 * AB_ROW + ks * 32, a0, a1, a2, a3);
                mma16816(acc[i][0], a0, a1, a2, a3, b[0], b[2]);
                mma16816(acc[i][1], a0, a1, a2, a3, b[1], b[3]);
                mma16816(acc[i][2], a0, a1, a2, a3, b[4], b[6]);
                mma16816(acc[i][3], a0, a1, a2, a3, b[5], b[7]);
            }
        }

        if (kc == 2) {   // tile K fully accumulated: fold into running mins
            const int colT = (sp * TILES + jt) * 128;
            const int nb = colT + wc * 32 + 2 * (l & 3);
            const int mL = rowBase + wr * 64 + (l >> 2);
            const bool diagT = (colT == rowBase);
            #pragma unroll
            for (int j = 0; j < 4; j++) {
                const int n0 = nb + j * 8;
                const float2 s2 = *(const float2*)(g_sq2 + n0);
                #pragma unroll
                for (int i = 0; i < 4; i++) {
                    float v0 = s2.x - 2.f * acc[i][j][0];
                    float v1 = s2.y - 2.f * acc[i][j][1];
                    float v2 = s2.x - 2.f * acc[i][j][2];
                    float v3 = s2.y - 2.f * acc[i][j][3];
                    if (diagT) {
                        const int m0 = mL + i * 16, m1 = m0 + 8;
                        if (n0 == m0)     { g_posv[m0] = v0; v0 = CUDART_INF_F; }
                        if (n0 + 1 == m0) { g_posv[m0] = v1; v1 = CUDART_INF_F; }
                        if (n0 == m1)     { g_posv[m1] = v2; v2 = CUDART_INF_F; }
                        if (n0 + 1 == m1) { g_posv[m1] = v3; v3 = CUDART_INF_F; }
                    }
                    rminL[i] = fminf(rminL[i], fminf(v0, v1));
                    rminH[i] = fminf(rminH[i], fminf(v2, v3));
                    acc[i][j][0] = 0.f; acc[i][j][1] = 0.f;
                    acc[i][j][2] = 0.f; acc[i][j][3] = 0.f;
                }
            }
        }
    }

    // cross-lane (n-groups of 4) then cross-warp-column reduction
    #pragma unroll
    for (int i = 0; i < 4; i++) {
        float vL = rminL[i], vH = rminH[i];
        vL = fminf(vL, __shfl_xor_sync(0xffffffffu, vL, 1));
        vL = fminf(vL, __shfl_xor_sync(0xffffffffu, vL, 2));
        vH = fminf(vH, __shfl_xor_sync(0xffffffffu, vH, 1));
        vH = fminf(vH, __shfl_xor_sync(0xffffffffu, vH, 2));
        if ((l & 3) == 0) {
            const int r = wr * 64 + i * 16 + (l >> 2);
            partmin[wc * 128 + r]     = vL;
            partmin[wc * 128 + r + 8] = vH;
        }
    }
    __syncthreads();
    if (tid < 128) {
        float m = fminf(fminf(partmin[tid], partmin[128 + tid]),
                        fminf(partmin[256 + tid], partmin[384 + tid]));
        g_rowmin[sp][rowBase + tid] = m;
    }
}

// ---------------------------------------------------------------------------
__global__ void finalize_kernel(float* __restrict__ out) {
    __shared__ float red[256];
    const int tid = threadIdx.x;
    float s = 0.f;
    for (int i = tid; i < NROWS; i += 256) {
        float m = fminf(g_rowmin[0][i], g_rowmin[1][i]);
        const float sq1 = g_sq1[i];
        const float l = sqrtf(fmaxf(sq1 + g_posv[i], 0.f))
                      - sqrtf(fmaxf(sq1 + m, 0.f)) + MARGIN_F;
        s += fmaxf(l, 0.f);
    }
    red[tid] = s;
    __syncthreads();
    #pragma unroll
    for (int o = 128; o; o >>= 1) {
        if (tid < o) red[tid] += red[tid + o];
        __syncthreads();
    }
    if (tid == 0) out[0] = red[0] / (float)NROWS;
}

// ---------------------------------------------------------------------------
extern "C" void kernel_launch(void* const* d_in, const int* in_sizes, int n_in,
                              void* d_out, int out_size) {
    const float* z1 = (const float*)d_in[0];
    const float* z2 = (const float*)d_in[1];
    float* out = (float*)d_out;

    cudaFuncSetAttribute(tl_gemm_kernel,
                         cudaFuncAttributeMaxDynamicSharedMemorySize, SMEM_TOTAL);

    prep_kernel<<<NROWS / 8, 256>>>(z1, z2);
    tl_gemm_kernel<<<dim3(64, NSPLIT), 256, SMEM_TOTAL>>>();
    finalize_kernel<<<1, 256>>>(out);
}